// round 7
// baseline (speedup 1.0000x reference)
#include <cuda_runtime.h>
#include <cuda_fp16.h>
#include <cstdint>
#include <math.h>

// ---------------------------------------------------------------------------
// RWKV-v4 block: B=4, T=4096, C=2048, A=2048, FF=8192
// fp16 mma.sync (m16n8k16) GEMMs, fp32 accumulate, ldmatrix fragment loads,
// ks-level fragment double-buffering, cp.async 3-stage smem pipeline.
// ---------------------------------------------------------------------------

#define B_  4
#define T_  4096
#define C_  2048
#define A_  2048
#define FF_ 8192

#define BTCll ((long long)B_ * T_ * C_)   // 33,554,432
#define BTFll ((long long)B_ * T_ * FF_)  // 134,217,728
#define ACll  ((long long)A_ * C_)        // 4,194,304
#define FCll  ((long long)FF_ * C_)       // 16,777,216

// float-unit layout:
// xk_h,xv_h,xr_h (BTC/2 each) | kk,vv,sr (BTC each) | sy_h (BTC/2)
// | kf_h (BTF/2) | hW (all fp16 weights, (5AC+2FC)/2)
__device__ float g_buf[262144000LL];

// ---------------------------------------------------------------------------
// helpers
// ---------------------------------------------------------------------------
__device__ __forceinline__ uint32_t s2u(const void* p) {
    return (uint32_t)__cvta_generic_to_shared(p);
}

__device__ __forceinline__ void cpa16(uint32_t dst, const void* src) {
    asm volatile("cp.async.cg.shared.global [%0], [%1], 16;" :: "r"(dst), "l"(src));
}

__device__ __forceinline__ void mma16(float c[4], const unsigned a[4], const unsigned b[2]) {
    asm volatile(
        "mma.sync.aligned.m16n8k16.row.col.f32.f16.f16.f32 "
        "{%0,%1,%2,%3}, {%4,%5,%6,%7}, {%8,%9}, {%0,%1,%2,%3};"
        : "+f"(c[0]), "+f"(c[1]), "+f"(c[2]), "+f"(c[3])
        : "r"(a[0]), "r"(a[1]), "r"(a[2]), "r"(a[3]), "r"(b[0]), "r"(b[1]));
}

#define LDSM4(rf, addr) \
    asm volatile("ldmatrix.sync.aligned.m8n8.x4.shared.b16 {%0,%1,%2,%3}, [%4];" \
        : "=r"((rf)[0]), "=r"((rf)[1]), "=r"((rf)[2]), "=r"((rf)[3]) : "r"(addr))

// ---------------------------------------------------------------------------
// Weight conversion fp32 -> fp16 (2 launches total)
// ---------------------------------------------------------------------------
__global__ __launch_bounds__(256) void conv_att_kernel(
    const float* __restrict__ w0, const float* __restrict__ w1,
    const float* __restrict__ w2, const float* __restrict__ w3,
    __half* __restrict__ d)  // 4 segments of AC floats each
{
    long long i4 = (long long)blockIdx.x * 256 + threadIdx.x;   // float4 index
    const long long segq = ACll / 4;
    int seg = (int)(i4 / segq);
    long long loc = (i4 - (long long)seg * segq) * 4;
    const float* s = (seg == 0) ? w0 : (seg == 1) ? w1 : (seg == 2) ? w2 : w3;
    float4 v = *(const float4*)(s + loc);
    __half2* o = (__half2*)(d + (long long)seg * ACll + loc);
    o[0] = __floats2half2_rn(v.x, v.y);
    o[1] = __floats2half2_rn(v.z, v.w);
}

__global__ __launch_bounds__(256) void conv_ffn_kernel(
    const float* __restrict__ wkf, const float* __restrict__ wrf,
    const float* __restrict__ wvf, __half* __restrict__ d)  // FC, AC, FC
{
    long long i4 = (long long)blockIdx.x * 256 + threadIdx.x;
    const long long q0 = FCll / 4, q1 = q0 + ACll / 4;
    const float* s;
    long long loc, dof;
    if (i4 < q0)      { s = wkf; loc = i4 * 4;        dof = loc; }
    else if (i4 < q1) { s = wrf; loc = (i4 - q0) * 4; dof = FCll + loc; }
    else              { s = wvf; loc = (i4 - q1) * 4; dof = FCll + ACll + loc; }
    float4 v = *(const float4*)(s + loc);
    __half2* o = (__half2*)(d + dof);
    o[0] = __floats2half2_rn(v.x, v.y);
    o[1] = __floats2half2_rn(v.z, v.w);
}

// ---------------------------------------------------------------------------
// Block reduce of 4 values (256 threads)
// ---------------------------------------------------------------------------
__device__ __forceinline__ void blockReduce4(float& a, float& b, float& c, float& d) {
    #pragma unroll
    for (int o = 16; o > 0; o >>= 1) {
        a += __shfl_down_sync(0xffffffffu, a, o);
        b += __shfl_down_sync(0xffffffffu, b, o);
        c += __shfl_down_sync(0xffffffffu, c, o);
        d += __shfl_down_sync(0xffffffffu, d, o);
    }
    __shared__ float sh[8][4];
    int w = threadIdx.x >> 5, l = threadIdx.x & 31;
    if (l == 0) { sh[w][0] = a; sh[w][1] = b; sh[w][2] = c; sh[w][3] = d; }
    __syncthreads();
    if (threadIdx.x == 0) {
        float ta = 0, tb = 0, tc = 0, td = 0;
        #pragma unroll
        for (int i = 0; i < 8; i++) { ta += sh[i][0]; tb += sh[i][1]; tc += sh[i][2]; td += sh[i][3]; }
        sh[0][0] = ta; sh[0][1] = tb; sh[0][2] = tc; sh[0][3] = td;
    }
    __syncthreads();
    a = sh[0][0]; b = sh[0][1]; c = sh[0][2]; d = sh[0][3];
}

// ---------------------------------------------------------------------------
// LayerNorm + shift mix -> fp16 outputs (GEMM A operands)
// ---------------------------------------------------------------------------
template <int NMIX>
__global__ __launch_bounds__(256) void ln_mix_kernel(
    const float* __restrict__ x, const float* __restrict__ shift_in,
    const float* __restrict__ gw, const float* __restrict__ bw,
    const float* __restrict__ m0, const float* __restrict__ m1, const float* __restrict__ m2,
    __half* __restrict__ o0, __half* __restrict__ o1, __half* __restrict__ o2,
    float* __restrict__ shift_out)
{
    const int bt = blockIdx.x;
    const int b = bt / T_, t = bt % T_;
    const int tid = threadIdx.x;
    const float* xr = x + (long long)bt * C_;

    float cur[8], prv[8];
    float s1 = 0.f, s2 = 0.f, p1 = 0.f, p2 = 0.f;
    #pragma unroll
    for (int i = 0; i < 8; i++) {
        int c = tid + i * 256;
        float v = xr[c];
        cur[i] = v; s1 += v; s2 += v * v;
        if (t > 0) {
            float w = xr[c - C_];
            prv[i] = w; p1 += w; p2 += w * w;
        } else prv[i] = 0.f;
    }
    blockReduce4(s1, s2, p1, p2);
    const float inv = 1.f / (float)C_;
    float mu = s1 * inv;
    float rs = rsqrtf(s2 * inv - mu * mu + 1e-5f);
    float mup = 0.f, rsp = 0.f;
    if (t > 0) {
        mup = p1 * inv;
        rsp = rsqrtf(p2 * inv - mup * mup + 1e-5f);
    }
    long long o = (long long)bt * C_;
    #pragma unroll
    for (int i = 0; i < 8; i++) {
        int c = tid + i * 256;
        float gg = gw[c], bb = bw[c];
        float xn = (cur[i] - mu) * rs * gg + bb;
        float xx = (t > 0) ? ((prv[i] - mup) * rsp * gg + bb)
                           : shift_in[(long long)b * C_ + c];
        float a0 = m0[c]; o0[o + c] = __float2half_rn(xn * a0 + xx * (1.f - a0));
        float a1 = m1[c]; o1[o + c] = __float2half_rn(xn * a1 + xx * (1.f - a1));
        if (NMIX == 3) { float a2 = m2[c]; o2[o + c] = __float2half_rn(xn * a2 + xx * (1.f - a2)); }
        if (t == T_ - 1) shift_out[(long long)b * C_ + c] = xn;
    }
}

// ---------------------------------------------------------------------------
// WKV scan: one thread per (b,channel); sy emitted as fp16 for the Wo GEMM
// ---------------------------------------------------------------------------
__global__ __launch_bounds__(64) void wkv_scan_kernel(
    const float* __restrict__ k, const float* __restrict__ v,
    const float* __restrict__ sr,
    const float* __restrict__ td, const float* __restrict__ tf,
    const float* __restrict__ state,
    __half* __restrict__ sy, float* __restrict__ out_wkv)
{
    int i = blockIdx.x * blockDim.x + threadIdx.x;  // b*A + a
    int b = i / A_, a = i % A_;
    float w = -expf(td[a]);
    float u = tf[a];
    long long so = ((long long)b * C_ + a) * 3;
    float aa = state[so + 0];
    float bb = state[so + 1];
    float pp = state[so + 2];
    long long o = (long long)b * T_ * A_ + a;
    float kt = k[o], vt = v[o], rt = sr[o];
    for (int t = 0; t < T_; t++) {
        long long on = o + A_;
        float kn = 0.f, vn = 0.f, rn = 0.f;
        if (t + 1 < T_) { kn = k[on]; vn = v[on]; rn = sr[on]; }
        float ww = u + kt;
        float p  = fmaxf(pp, ww);
        float e1 = __expf(pp - p);
        float e2 = __expf(ww - p);
        float y  = __fdividef(e1 * aa + e2 * vt, e1 * bb + e2);
        sy[o] = __float2half_rn(rt * y);
        float ww2 = pp + w;
        float p2  = fmaxf(ww2, kt);
        e1 = __expf(ww2 - p2);
        e2 = __expf(kt - p2);
        aa = e1 * aa + e2 * vt;
        bb = e1 * bb + e2;
        pp = p2;
        o = on; kt = kn; vt = vn; rt = rn;
    }
    out_wkv[so + 0] = aa;
    out_wkv[so + 1] = bb;
    out_wkv[so + 2] = pp;
}

// ---------------------------------------------------------------------------
// FP16 NT GEMM via mma.sync m16n8k16: out[m,n] = sum_k A[m,k]*B[n,k]
// CTA 128x128x64, 128 threads (4 warps, warp tile 64x64), cp.async 3-stage,
// ldmatrix fragment loads, ks double-buffered fragments.
// MODE: 0=store f32, 1=sigmoid f32, 2=relu^2 -> fp16, 3=base+acc, 4=base+mul*acc
// ---------------------------------------------------------------------------
#define GBK   64
#define HSTR  72                               // halfs per smem row (64+8 pad)
#define STG_H (2 * 128 * HSTR)                 // A+B rows per stage, in halfs
#define NSTG  3
#define GEMM_SMEM (NSTG * STG_H * 2)           // 110592 B -> 2 CTAs/SM

template <int MODE>
__global__ __launch_bounds__(128, 2) void gemm_h(
    const __half* __restrict__ Ag, const __half* __restrict__ Bg,
    void* __restrict__ Ogv,
    const float* __restrict__ base, const float* __restrict__ mul,
    int M, int N, int K, int tiles_n)
{
    extern __shared__ __half sm[];

    const int tid  = threadIdx.x;
    const int lane = tid & 31;
    const int warp = tid >> 5;            // 0..3
    const int wm   = (warp & 1) * 64;
    const int wn   = (warp >> 1) * 64;
    const int gid  = lane >> 2;           // 0..7
    const int tig  = lane & 3;            // 0..3

    // rasterization: groups of 16 M-tiles; consecutive blocks share B tile
    const int per = 16 * tiles_n;
    const int grp = blockIdx.x / per, rem = blockIdx.x % per;
    const int mt = grp * 16 + (rem % 16);
    const int nt = rem / 16;
    const long long bm0 = (long long)mt * 128, bn0 = (long long)nt * 128;

    const int ldr = tid >> 3;             // 0..15 base row
    const int ldh = (tid & 7) * 8;        // half col {0,8,...,56}

    const uint32_t sbase = s2u(sm);

    // ldmatrix per-thread offsets (bytes). q = address-group, r = row in group.
    const int q = lane >> 3, r = lane & 7;
    const uint32_t aoff = (uint32_t)(((wm + (q & 1) * 8 + r) * HSTR + (q >> 1) * 8) * 2);
    const uint32_t boff = (uint32_t)((128 * HSTR + (wn + (q >> 1) * 8 + r) * HSTR + (q & 1) * 8) * 2);

    auto load_stage = [&](int j) {
        __half* As = sm + (j % NSTG) * STG_H;
        __half* Bs = As + 128 * HSTR;
        const long long k0 = (long long)j * GBK;
        const __half* Ap = Ag + (bm0 + ldr) * K + k0 + ldh;
        const __half* Bp = Bg + (bn0 + ldr) * K + k0 + ldh;
        uint32_t da = s2u(As + ldr * HSTR + ldh);
        uint32_t db = s2u(Bs + ldr * HSTR + ldh);
        #pragma unroll
        for (int i = 0; i < 8; i++) {
            cpa16(da + i * 16 * HSTR * 2, Ap + (long long)i * 16 * K);
            cpa16(db + i * 16 * HSTR * 2, Bp + (long long)i * 16 * K);
        }
    };

    float acc[4][8][4];
    #pragma unroll
    for (int mi = 0; mi < 4; mi++)
        #pragma unroll
        for (int ni = 0; ni < 8; ni++)
            #pragma unroll
            for (int qq = 0; qq < 4; qq++) acc[mi][ni][qq] = 0.f;

    const int nk = K >> 6;
    load_stage(0);
    asm volatile("cp.async.commit_group;" ::: "memory");
    load_stage(1);
    asm volatile("cp.async.commit_group;" ::: "memory");

    unsigned af[2][4][4];     // [buf][mi][frag]
    unsigned bf[2][4][4];     // [buf][ni-pair][frag] = {b[2p][0],b[2p][1],b[2p+1][0],b[2p+1][1]}

    for (int j = 0; j < nk; j++) {
        asm volatile("cp.async.wait_group 1;" ::: "memory");
        __syncthreads();
        if (j + 2 < nk) load_stage(j + 2);
        asm volatile("cp.async.commit_group;" ::: "memory");

        const uint32_t sa = sbase + (uint32_t)((j % NSTG) * STG_H * 2) + aoff;
        const uint32_t sb = sbase + (uint32_t)((j % NSTG) * STG_H * 2) + boff;

        // prologue: fragments for ks=0
        #pragma unroll
        for (int mi = 0; mi < 4; mi++) LDSM4(af[0][mi], sa + mi * (16 * HSTR * 2));
        #pragma unroll
        for (int pi = 0; pi < 4; pi++) LDSM4(bf[0][pi], sb + pi * (16 * HSTR * 2));

        #pragma unroll
        for (int ks = 0; ks < 4; ks++) {
            const int cb = ks & 1, nb = cb ^ 1;
            if (ks < 3) {
                const uint32_t ko = (uint32_t)((ks + 1) * 32);   // 16 halfs
                #pragma unroll
                for (int mi = 0; mi < 4; mi++) LDSM4(af[nb][mi], sa + mi * (16 * HSTR * 2) + ko);
                #pragma unroll
                for (int pi = 0; pi < 4; pi++) LDSM4(bf[nb][pi], sb + pi * (16 * HSTR * 2) + ko);
            }
            #pragma unroll
            for (int mi = 0; mi < 4; mi++)
                #pragma unroll
                for (int ni = 0; ni < 8; ni++)
                    mma16(acc[mi][ni], af[cb][mi], &bf[cb][ni >> 1][(ni & 1) * 2]);
        }
    }

    // epilogue
    #pragma unroll
    for (int mi = 0; mi < 4; mi++) {
        #pragma unroll
        for (int ni = 0; ni < 8; ni++) {
            long long row = bm0 + wm + mi * 16 + gid;
            long long col = bn0 + wn + ni * 8 + 2 * tig;
            long long i0 = row * N + col;
            long long i1 = (row + 8) * N + col;
            float v00 = acc[mi][ni][0], v01 = acc[mi][ni][1];
            float v10 = acc[mi][ni][2], v11 = acc[mi][ni][3];
            if (MODE == 1) {
                v00 = 1.f / (1.f + __expf(-v00)); v01 = 1.f / (1.f + __expf(-v01));
                v10 = 1.f / (1.f + __expf(-v10)); v11 = 1.f / (1.f + __expf(-v11));
            } else if (MODE == 3) {
                v00 += base[i0]; v01 += base[i0 + 1];
                v10 += base[i1]; v11 += base[i1 + 1];
            } else if (MODE == 4) {
                v00 = fmaf(mul[i0], v00, base[i0]);
                v01 = fmaf(mul[i0 + 1], v01, base[i0 + 1]);
                v10 = fmaf(mul[i1], v10, base[i1]);
                v11 = fmaf(mul[i1 + 1], v11, base[i1 + 1]);
            }
            if (MODE == 2) {
                __half* Og = (__half*)Ogv;
                float t00 = fmaxf(v00, 0.f), t01 = fmaxf(v01, 0.f);
                float t10 = fmaxf(v10, 0.f), t11 = fmaxf(v11, 0.f);
                *(__half2*)(Og + i0) = __floats2half2_rn(t00 * t00, t01 * t01);
                *(__half2*)(Og + i1) = __floats2half2_rn(t10 * t10, t11 * t11);
            } else {
                float* Og = (float*)Ogv;
                *(float2*)(Og + i0) = make_float2(v00, v01);
                *(float2*)(Og + i1) = make_float2(v10, v11);
            }
        }
    }
}

// ---------------------------------------------------------------------------
// Launcher
// ---------------------------------------------------------------------------
extern "C" void kernel_launch(void* const* d_in, const int* in_sizes, int n_in,
                              void* d_out, int out_size)
{
    const float* x    = (const float*)d_in[0];
    const float* tm   = (const float*)d_in[1];
    const float* st   = (const float*)d_in[2];
    const float* cm   = (const float*)d_in[3];
    const float* g1   = (const float*)d_in[4];
    const float* b1   = (const float*)d_in[5];
    const float* g2   = (const float*)d_in[6];
    const float* b2   = (const float*)d_in[7];
    const float* td   = (const float*)d_in[8];
    const float* tfst = (const float*)d_in[9];
    const float* amk  = (const float*)d_in[10];
    const float* amv  = (const float*)d_in[11];
    const float* amr  = (const float*)d_in[12];
    const float* Wk   = (const float*)d_in[13];
    const float* Wv   = (const float*)d_in[14];
    const float* Wr   = (const float*)d_in[15];
    const float* Wo   = (const float*)d_in[16];
    const float* fmk  = (const float*)d_in[17];
    const float* fmr  = (const float*)d_in[18];
    const float* Wkf  = (const float*)d_in[19];
    const float* Wrf  = (const float*)d_in[20];
    const float* Wvf  = (const float*)d_in[21];

    float* out     = (float*)d_out;
    float* out_x   = out;
    float* out_wkv = out + BTCll;
    float* out_tm  = out_wkv + (long long)B_ * C_ * 3;
    float* out_cm  = out_tm + (long long)B_ * C_;

    float* buf = nullptr;
    cudaGetSymbolAddress((void**)&buf, g_buf);
    __half* xk_h = (__half*)(buf);
    __half* xv_h = xk_h + BTCll;
    __half* xr_h = xv_h + BTCll;
    float*  kk   = buf + 3 * (BTCll / 2);
    float*  vv   = kk + BTCll;
    float*  sr   = vv + BTCll;
    __half* sy_h = (__half*)(sr + BTCll);
    __half* kf_h = sy_h + BTCll;
    __half* hW   = kf_h + BTFll;
    __half* hWk  = hW;
    __half* hWv  = hWk + ACll;
    __half* hWr  = hWv + ACll;
    __half* hWo  = hWr + ACll;
    __half* hWkf = hWo + ACll;
    __half* hWrf = hWkf + FCll;
    __half* hWvf = hWrf + ACll;

    cudaFuncSetAttribute((const void*)gemm_h<0>, cudaFuncAttributeMaxDynamicSharedMemorySize, GEMM_SMEM);
    cudaFuncSetAttribute((const void*)gemm_h<1>, cudaFuncAttributeMaxDynamicSharedMemorySize, GEMM_SMEM);
    cudaFuncSetAttribute((const void*)gemm_h<2>, cudaFuncAttributeMaxDynamicSharedMemorySize, GEMM_SMEM);
    cudaFuncSetAttribute((const void*)gemm_h<3>, cudaFuncAttributeMaxDynamicSharedMemorySize, GEMM_SMEM);
    cudaFuncSetAttribute((const void*)gemm_h<4>, cudaFuncAttributeMaxDynamicSharedMemorySize, GEMM_SMEM);

    const int M = B_ * T_;
    const int tm_ = M / 128;

    // weight fp32 -> fp16 (2 launches)
    conv_att_kernel<<<(int)(4 * ACll / 4 / 256), 256>>>(Wk, Wv, Wr, Wo, hW);
    conv_ffn_kernel<<<(int)((2 * FCll + ACll) / 4 / 256), 256>>>(Wkf, Wrf, Wvf, hWkf);

    // --- attention path ---
    ln_mix_kernel<3><<<M, 256>>>(x, tm, g1, b1, amk, amv, amr, xk_h, xv_h, xr_h, out_tm);

    gemm_h<0><<<tm_ * (A_ / 128), 128, GEMM_SMEM>>>(xk_h, hWk, kk, nullptr, nullptr, M, A_, C_, A_ / 128);
    gemm_h<0><<<tm_ * (A_ / 128), 128, GEMM_SMEM>>>(xv_h, hWv, vv, nullptr, nullptr, M, A_, C_, A_ / 128);
    gemm_h<1><<<tm_ * (A_ / 128), 128, GEMM_SMEM>>>(xr_h, hWr, sr, nullptr, nullptr, M, A_, C_, A_ / 128);

    wkv_scan_kernel<<<(B_ * A_) / 64, 64>>>(kk, vv, sr, td, tfst, st, sy_h, out_wkv);

    gemm_h<3><<<tm_ * (C_ / 128), 128, GEMM_SMEM>>>(sy_h, hWo, out_x, x, nullptr, M, C_, A_, C_ / 128);

    // --- ffn path ---
    ln_mix_kernel<2><<<M, 256>>>(out_x, cm, g2, b2, fmk, fmr, nullptr, xk_h, xr_h, nullptr, out_cm);

    gemm_h<2><<<tm_ * (FF_ / 128), 128, GEMM_SMEM>>>(xk_h, hWkf, kf_h, nullptr, nullptr, M, FF_, C_, FF_ / 128);
    gemm_h<1><<<tm_ * (C_ / 128), 128, GEMM_SMEM>>>(xr_h, hWrf, vv, nullptr, nullptr, M, C_, C_, C_ / 128);
    gemm_h<4><<<tm_ * (C_ / 128), 128, GEMM_SMEM>>>(kf_h, hWvf, out_x, out_x, vv, M, C_, FF_, C_ / 128);
}

// round 12
// speedup vs baseline: 1.4623x; 1.4623x over previous
#include <cuda_runtime.h>
#include <cuda_fp16.h>
#include <cstdint>
#include <math.h>

// ---------------------------------------------------------------------------
// RWKV-v4 block: B=4, T=4096, C=2048, A=2048, FF=8192
// fp16 mma.sync (m16n8k16) GEMMs, fp32 accumulate, single-buffered ldmatrix
// fragment loads (low register pressure), cp.async 3-stage smem pipeline.
// ---------------------------------------------------------------------------

#define B_  4
#define T_  4096
#define C_  2048
#define A_  2048
#define FF_ 8192

#define BTCll ((long long)B_ * T_ * C_)   // 33,554,432
#define BTFll ((long long)B_ * T_ * FF_)  // 134,217,728
#define ACll  ((long long)A_ * C_)        // 4,194,304
#define FCll  ((long long)FF_ * C_)       // 16,777,216

// float-unit layout:
// xk_h,xv_h,xr_h (BTC/2 each) | kk,vv,sr (BTC each) | sy_h (BTC/2)
// | kf_h (BTF/2) | hW (all fp16 weights, (5AC+2FC)/2)
__device__ float g_buf[262144000LL];

// ---------------------------------------------------------------------------
// helpers
// ---------------------------------------------------------------------------
__device__ __forceinline__ uint32_t s2u(const void* p) {
    return (uint32_t)__cvta_generic_to_shared(p);
}

__device__ __forceinline__ void cpa16(uint32_t dst, const void* src) {
    asm volatile("cp.async.cg.shared.global [%0], [%1], 16;" :: "r"(dst), "l"(src));
}

__device__ __forceinline__ void mma16(float c[4], const unsigned a[4], const unsigned b[2]) {
    asm volatile(
        "mma.sync.aligned.m16n8k16.row.col.f32.f16.f16.f32 "
        "{%0,%1,%2,%3}, {%4,%5,%6,%7}, {%8,%9}, {%0,%1,%2,%3};"
        : "+f"(c[0]), "+f"(c[1]), "+f"(c[2]), "+f"(c[3])
        : "r"(a[0]), "r"(a[1]), "r"(a[2]), "r"(a[3]), "r"(b[0]), "r"(b[1]));
}

#define LDSM4(rf, addr) \
    asm volatile("ldmatrix.sync.aligned.m8n8.x4.shared.b16 {%0,%1,%2,%3}, [%4];" \
        : "=r"((rf)[0]), "=r"((rf)[1]), "=r"((rf)[2]), "=r"((rf)[3]) : "r"(addr))

// ---------------------------------------------------------------------------
// Weight conversion fp32 -> fp16 (2 launches total)
// ---------------------------------------------------------------------------
__global__ __launch_bounds__(256) void conv_att_kernel(
    const float* __restrict__ w0, const float* __restrict__ w1,
    const float* __restrict__ w2, const float* __restrict__ w3,
    __half* __restrict__ d)  // 4 segments of AC floats each
{
    long long i4 = (long long)blockIdx.x * 256 + threadIdx.x;   // float4 index
    const long long segq = ACll / 4;
    int seg = (int)(i4 / segq);
    long long loc = (i4 - (long long)seg * segq) * 4;
    const float* s = (seg == 0) ? w0 : (seg == 1) ? w1 : (seg == 2) ? w2 : w3;
    float4 v = *(const float4*)(s + loc);
    __half2* o = (__half2*)(d + (long long)seg * ACll + loc);
    o[0] = __floats2half2_rn(v.x, v.y);
    o[1] = __floats2half2_rn(v.z, v.w);
}

__global__ __launch_bounds__(256) void conv_ffn_kernel(
    const float* __restrict__ wkf, const float* __restrict__ wrf,
    const float* __restrict__ wvf, __half* __restrict__ d)  // FC, AC, FC
{
    long long i4 = (long long)blockIdx.x * 256 + threadIdx.x;
    const long long q0 = FCll / 4, q1 = q0 + ACll / 4;
    const float* s;
    long long loc, dof;
    if (i4 < q0)      { s = wkf; loc = i4 * 4;        dof = loc; }
    else if (i4 < q1) { s = wrf; loc = (i4 - q0) * 4; dof = FCll + loc; }
    else              { s = wvf; loc = (i4 - q1) * 4; dof = FCll + ACll + loc; }
    float4 v = *(const float4*)(s + loc);
    __half2* o = (__half2*)(d + dof);
    o[0] = __floats2half2_rn(v.x, v.y);
    o[1] = __floats2half2_rn(v.z, v.w);
}

// ---------------------------------------------------------------------------
// Block reduce of 4 values (256 threads)
// ---------------------------------------------------------------------------
__device__ __forceinline__ void blockReduce4(float& a, float& b, float& c, float& d) {
    #pragma unroll
    for (int o = 16; o > 0; o >>= 1) {
        a += __shfl_down_sync(0xffffffffu, a, o);
        b += __shfl_down_sync(0xffffffffu, b, o);
        c += __shfl_down_sync(0xffffffffu, c, o);
        d += __shfl_down_sync(0xffffffffu, d, o);
    }
    __shared__ float sh[8][4];
    int w = threadIdx.x >> 5, l = threadIdx.x & 31;
    if (l == 0) { sh[w][0] = a; sh[w][1] = b; sh[w][2] = c; sh[w][3] = d; }
    __syncthreads();
    if (threadIdx.x == 0) {
        float ta = 0, tb = 0, tc = 0, td = 0;
        #pragma unroll
        for (int i = 0; i < 8; i++) { ta += sh[i][0]; tb += sh[i][1]; tc += sh[i][2]; td += sh[i][3]; }
        sh[0][0] = ta; sh[0][1] = tb; sh[0][2] = tc; sh[0][3] = td;
    }
    __syncthreads();
    a = sh[0][0]; b = sh[0][1]; c = sh[0][2]; d = sh[0][3];
}

// ---------------------------------------------------------------------------
// LayerNorm + shift mix -> fp16 outputs (GEMM A operands)
// ---------------------------------------------------------------------------
template <int NMIX>
__global__ __launch_bounds__(256) void ln_mix_kernel(
    const float* __restrict__ x, const float* __restrict__ shift_in,
    const float* __restrict__ gw, const float* __restrict__ bw,
    const float* __restrict__ m0, const float* __restrict__ m1, const float* __restrict__ m2,
    __half* __restrict__ o0, __half* __restrict__ o1, __half* __restrict__ o2,
    float* __restrict__ shift_out)
{
    const int bt = blockIdx.x;
    const int b = bt / T_, t = bt % T_;
    const int tid = threadIdx.x;
    const float* xr = x + (long long)bt * C_;

    float cur[8], prv[8];
    float s1 = 0.f, s2 = 0.f, p1 = 0.f, p2 = 0.f;
    #pragma unroll
    for (int i = 0; i < 8; i++) {
        int c = tid + i * 256;
        float v = xr[c];
        cur[i] = v; s1 += v; s2 += v * v;
        if (t > 0) {
            float w = xr[c - C_];
            prv[i] = w; p1 += w; p2 += w * w;
        } else prv[i] = 0.f;
    }
    blockReduce4(s1, s2, p1, p2);
    const float inv = 1.f / (float)C_;
    float mu = s1 * inv;
    float rs = rsqrtf(s2 * inv - mu * mu + 1e-5f);
    float mup = 0.f, rsp = 0.f;
    if (t > 0) {
        mup = p1 * inv;
        rsp = rsqrtf(p2 * inv - mup * mup + 1e-5f);
    }
    long long o = (long long)bt * C_;
    #pragma unroll
    for (int i = 0; i < 8; i++) {
        int c = tid + i * 256;
        float gg = gw[c], bb = bw[c];
        float xn = (cur[i] - mu) * rs * gg + bb;
        float xx = (t > 0) ? ((prv[i] - mup) * rsp * gg + bb)
                           : shift_in[(long long)b * C_ + c];
        float a0 = m0[c]; o0[o + c] = __float2half_rn(xn * a0 + xx * (1.f - a0));
        float a1 = m1[c]; o1[o + c] = __float2half_rn(xn * a1 + xx * (1.f - a1));
        if (NMIX == 3) { float a2 = m2[c]; o2[o + c] = __float2half_rn(xn * a2 + xx * (1.f - a2)); }
        if (t == T_ - 1) shift_out[(long long)b * C_ + c] = xn;
    }
}

// ---------------------------------------------------------------------------
// WKV scan: one thread per (b,channel); sy emitted as fp16 for the Wo GEMM
// ---------------------------------------------------------------------------
__global__ __launch_bounds__(64) void wkv_scan_kernel(
    const float* __restrict__ k, const float* __restrict__ v,
    const float* __restrict__ sr,
    const float* __restrict__ td, const float* __restrict__ tf,
    const float* __restrict__ state,
    __half* __restrict__ sy, float* __restrict__ out_wkv)
{
    int i = blockIdx.x * blockDim.x + threadIdx.x;  // b*A + a
    int b = i / A_, a = i % A_;
    float w = -expf(td[a]);
    float u = tf[a];
    long long so = ((long long)b * C_ + a) * 3;
    float aa = state[so + 0];
    float bb = state[so + 1];
    float pp = state[so + 2];
    long long o = (long long)b * T_ * A_ + a;
    float kt = k[o], vt = v[o], rt = sr[o];
    for (int t = 0; t < T_; t++) {
        long long on = o + A_;
        float kn = 0.f, vn = 0.f, rn = 0.f;
        if (t + 1 < T_) { kn = k[on]; vn = v[on]; rn = sr[on]; }
        float ww = u + kt;
        float p  = fmaxf(pp, ww);
        float e1 = __expf(pp - p);
        float e2 = __expf(ww - p);
        float y  = __fdividef(e1 * aa + e2 * vt, e1 * bb + e2);
        sy[o] = __float2half_rn(rt * y);
        float ww2 = pp + w;
        float p2  = fmaxf(ww2, kt);
        e1 = __expf(ww2 - p2);
        e2 = __expf(kt - p2);
        aa = e1 * aa + e2 * vt;
        bb = e1 * bb + e2;
        pp = p2;
        o = on; kt = kn; vt = vn; rt = rn;
    }
    out_wkv[so + 0] = aa;
    out_wkv[so + 1] = bb;
    out_wkv[so + 2] = pp;
}

// ---------------------------------------------------------------------------
// FP16 NT GEMM via mma.sync m16n8k16: out[m,n] = sum_k A[m,k]*B[n,k]
// CTA 128x128x64, 128 threads (4 warps, warp tile 64x64), cp.async 3-stage,
// single-buffered ldmatrix fragment loads.
// MODE: 0=store f32, 1=sigmoid f32, 2=relu^2 -> fp16, 3=base+acc, 4=base+mul*acc
// ---------------------------------------------------------------------------
#define GBK   64
#define HSTR  72                               // halfs per smem row (64+8 pad)
#define STG_H (2 * 128 * HSTR)                 // A+B rows per stage, in halfs
#define NSTG  3
#define GEMM_SMEM (NSTG * STG_H * 2)           // 110592 B -> 2 CTAs/SM

template <int MODE>
__global__ __launch_bounds__(128, 2) void gemm_h(
    const __half* __restrict__ Ag, const __half* __restrict__ Bg,
    void* __restrict__ Ogv,
    const float* __restrict__ base, const float* __restrict__ mul,
    int M, int N, int K, int tiles_n)
{
    extern __shared__ __half sm[];

    const int tid  = threadIdx.x;
    const int lane = tid & 31;
    const int warp = tid >> 5;            // 0..3
    const int wm   = (warp & 1) * 64;
    const int wn   = (warp >> 1) * 64;
    const int gid  = lane >> 2;           // 0..7
    const int tig  = lane & 3;            // 0..3

    // rasterization: groups of 16 M-tiles; consecutive blocks share B tile
    const int per = 16 * tiles_n;
    const int grp = blockIdx.x / per, rem = blockIdx.x % per;
    const int mt = grp * 16 + (rem % 16);
    const int nt = rem / 16;
    const long long bm0 = (long long)mt * 128, bn0 = (long long)nt * 128;

    const int ldr = tid >> 3;             // 0..15 base row
    const int ldh = (tid & 7) * 8;        // half col {0,8,...,56}

    const uint32_t sbase = s2u(sm);

    // ldmatrix per-thread offsets (bytes). q = address-group, r = row in group.
    const int q = lane >> 3, r = lane & 7;
    const uint32_t aoff = (uint32_t)(((wm + (q & 1) * 8 + r) * HSTR + (q >> 1) * 8) * 2);
    const uint32_t boff = (uint32_t)((128 * HSTR + (wn + (q >> 1) * 8 + r) * HSTR + (q & 1) * 8) * 2);

    auto load_stage = [&](int j) {
        __half* As = sm + (j % NSTG) * STG_H;
        __half* Bs = As + 128 * HSTR;
        const long long k0 = (long long)j * GBK;
        const __half* Ap = Ag + (bm0 + ldr) * K + k0 + ldh;
        const __half* Bp = Bg + (bn0 + ldr) * K + k0 + ldh;
        uint32_t da = s2u(As + ldr * HSTR + ldh);
        uint32_t db = s2u(Bs + ldr * HSTR + ldh);
        #pragma unroll
        for (int i = 0; i < 8; i++) {
            cpa16(da + i * 16 * HSTR * 2, Ap + (long long)i * 16 * K);
            cpa16(db + i * 16 * HSTR * 2, Bp + (long long)i * 16 * K);
        }
    };

    float acc[4][8][4];
    #pragma unroll
    for (int mi = 0; mi < 4; mi++)
        #pragma unroll
        for (int ni = 0; ni < 8; ni++)
            #pragma unroll
            for (int qq = 0; qq < 4; qq++) acc[mi][ni][qq] = 0.f;

    const int nk = K >> 6;
    load_stage(0);
    asm volatile("cp.async.commit_group;" ::: "memory");
    load_stage(1);
    asm volatile("cp.async.commit_group;" ::: "memory");

    unsigned af[4][4];        // [mi][frag]
    unsigned bf[4][4];        // [ni-pair][frag] = {b[2p][0],b[2p][1],b[2p+1][0],b[2p+1][1]}

    for (int j = 0; j < nk; j++) {
        asm volatile("cp.async.wait_group 1;" ::: "memory");
        __syncthreads();
        if (j + 2 < nk) load_stage(j + 2);
        asm volatile("cp.async.commit_group;" ::: "memory");

        const uint32_t sa = sbase + (uint32_t)((j % NSTG) * STG_H * 2) + aoff;
        const uint32_t sb = sbase + (uint32_t)((j % NSTG) * STG_H * 2) + boff;

        #pragma unroll
        for (int ks = 0; ks < 4; ks++) {
            const uint32_t ko = (uint32_t)(ks * 32);   // 16 halfs in bytes
            #pragma unroll
            for (int mi = 0; mi < 4; mi++) LDSM4(af[mi], sa + mi * (16 * HSTR * 2) + ko);
            #pragma unroll
            for (int pi = 0; pi < 4; pi++) LDSM4(bf[pi], sb + pi * (16 * HSTR * 2) + ko);
            #pragma unroll
            for (int mi = 0; mi < 4; mi++)
                #pragma unroll
                for (int ni = 0; ni < 8; ni++)
                    mma16(acc[mi][ni], af[mi], &bf[ni >> 1][(ni & 1) * 2]);
        }
    }

    // epilogue
    #pragma unroll
    for (int mi = 0; mi < 4; mi++) {
        #pragma unroll
        for (int ni = 0; ni < 8; ni++) {
            long long row = bm0 + wm + mi * 16 + gid;
            long long col = bn0 + wn + ni * 8 + 2 * tig;
            long long i0 = row * N + col;
            long long i1 = (row + 8) * N + col;
            float v00 = acc[mi][ni][0], v01 = acc[mi][ni][1];
            float v10 = acc[mi][ni][2], v11 = acc[mi][ni][3];
            if (MODE == 1) {
                v00 = 1.f / (1.f + __expf(-v00)); v01 = 1.f / (1.f + __expf(-v01));
                v10 = 1.f / (1.f + __expf(-v10)); v11 = 1.f / (1.f + __expf(-v11));
            } else if (MODE == 3) {
                v00 += base[i0]; v01 += base[i0 + 1];
                v10 += base[i1]; v11 += base[i1 + 1];
            } else if (MODE == 4) {
                v00 = fmaf(mul[i0], v00, base[i0]);
                v01 = fmaf(mul[i0 + 1], v01, base[i0 + 1]);
                v10 = fmaf(mul[i1], v10, base[i1]);
                v11 = fmaf(mul[i1 + 1], v11, base[i1 + 1]);
            }
            if (MODE == 2) {
                __half* Og = (__half*)Ogv;
                float t00 = fmaxf(v00, 0.f), t01 = fmaxf(v01, 0.f);
                float t10 = fmaxf(v10, 0.f), t11 = fmaxf(v11, 0.f);
                *(__half2*)(Og + i0) = __floats2half2_rn(t00 * t00, t01 * t01);
                *(__half2*)(Og + i1) = __floats2half2_rn(t10 * t10, t11 * t11);
            } else {
                float* Og = (float*)Ogv;
                *(float2*)(Og + i0) = make_float2(v00, v01);
                *(float2*)(Og + i1) = make_float2(v10, v11);
            }
        }
    }
}

// ---------------------------------------------------------------------------
// Launcher
// ---------------------------------------------------------------------------
extern "C" void kernel_launch(void* const* d_in, const int* in_sizes, int n_in,
                              void* d_out, int out_size)
{
    const float* x    = (const float*)d_in[0];
    const float* tm   = (const float*)d_in[1];
    const float* st   = (const float*)d_in[2];
    const float* cm   = (const float*)d_in[3];
    const float* g1   = (const float*)d_in[4];
    const float* b1   = (const float*)d_in[5];
    const float* g2   = (const float*)d_in[6];
    const float* b2   = (const float*)d_in[7];
    const float* td   = (const float*)d_in[8];
    const float* tfst = (const float*)d_in[9];
    const float* amk  = (const float*)d_in[10];
    const float* amv  = (const float*)d_in[11];
    const float* amr  = (const float*)d_in[12];
    const float* Wk   = (const float*)d_in[13];
    const float* Wv   = (const float*)d_in[14];
    const float* Wr   = (const float*)d_in[15];
    const float* Wo   = (const float*)d_in[16];
    const float* fmk  = (const float*)d_in[17];
    const float* fmr  = (const float*)d_in[18];
    const float* Wkf  = (const float*)d_in[19];
    const float* Wrf  = (const float*)d_in[20];
    const float* Wvf  = (const float*)d_in[21];

    float* out     = (float*)d_out;
    float* out_x   = out;
    float* out_wkv = out + BTCll;
    float* out_tm  = out_wkv + (long long)B_ * C_ * 3;
    float* out_cm  = out_tm + (long long)B_ * C_;

    float* buf = nullptr;
    cudaGetSymbolAddress((void**)&buf, g_buf);
    __half* xk_h = (__half*)(buf);
    __half* xv_h = xk_h + BTCll;
    __half* xr_h = xv_h + BTCll;
    float*  kk   = buf + 3 * (BTCll / 2);
    float*  vv   = kk + BTCll;
    float*  sr   = vv + BTCll;
    __half* sy_h = (__half*)(sr + BTCll);
    __half* kf_h = sy_h + BTCll;
    __half* hW   = kf_h + BTFll;
    __half* hWk  = hW;
    __half* hWv  = hWk + ACll;
    __half* hWr  = hWv + ACll;
    __half* hWo  = hWr + ACll;
    __half* hWkf = hWo + ACll;
    __half* hWrf = hWkf + FCll;
    __half* hWvf = hWrf + ACll;

    cudaFuncSetAttribute((const void*)gemm_h<0>, cudaFuncAttributeMaxDynamicSharedMemorySize, GEMM_SMEM);
    cudaFuncSetAttribute((const void*)gemm_h<1>, cudaFuncAttributeMaxDynamicSharedMemorySize, GEMM_SMEM);
    cudaFuncSetAttribute((const void*)gemm_h<2>, cudaFuncAttributeMaxDynamicSharedMemorySize, GEMM_SMEM);
    cudaFuncSetAttribute((const void*)gemm_h<3>, cudaFuncAttributeMaxDynamicSharedMemorySize, GEMM_SMEM);
    cudaFuncSetAttribute((const void*)gemm_h<4>, cudaFuncAttributeMaxDynamicSharedMemorySize, GEMM_SMEM);

    const int M = B_ * T_;
    const int tm_ = M / 128;

    // weight fp32 -> fp16 (2 launches)
    conv_att_kernel<<<(int)(4 * ACll / 4 / 256), 256>>>(Wk, Wv, Wr, Wo, hW);
    conv_ffn_kernel<<<(int)((2 * FCll + ACll) / 4 / 256), 256>>>(Wkf, Wrf, Wvf, hWkf);

    // --- attention path ---
    ln_mix_kernel<3><<<M, 256>>>(x, tm, g1, b1, amk, amv, amr, xk_h, xv_h, xr_h, out_tm);

    gemm_h<0><<<tm_ * (A_ / 128), 128, GEMM_SMEM>>>(xk_h, hWk, kk, nullptr, nullptr, M, A_, C_, A_ / 128);
    gemm_h<0><<<tm_ * (A_ / 128), 128, GEMM_SMEM>>>(xv_h, hWv, vv, nullptr, nullptr, M, A_, C_, A_ / 128);
    gemm_h<1><<<tm_ * (A_ / 128), 128, GEMM_SMEM>>>(xr_h, hWr, sr, nullptr, nullptr, M, A_, C_, A_ / 128);

    wkv_scan_kernel<<<(B_ * A_) / 64, 64>>>(kk, vv, sr, td, tfst, st, sy_h, out_wkv);

    gemm_h<3><<<tm_ * (C_ / 128), 128, GEMM_SMEM>>>(sy_h, hWo, out_x, x, nullptr, M, C_, A_, C_ / 128);

    // --- ffn path ---
    ln_mix_kernel<2><<<M, 256>>>(out_x, cm, g2, b2, fmk, fmr, nullptr, xk_h, xr_h, nullptr, out_cm);

    gemm_h<2><<<tm_ * (FF_ / 128), 128, GEMM_SMEM>>>(xk_h, hWkf, kf_h, nullptr, nullptr, M, FF_, C_, FF_ / 128);
    gemm_h<1><<<tm_ * (C_ / 128), 128, GEMM_SMEM>>>(xr_h, hWrf, vv, nullptr, nullptr, M, C_, C_, C_ / 128);
    gemm_h<4><<<tm_ * (C_ / 128), 128, GEMM_SMEM>>>(kf_h, hWvf, out_x, out_x, vv, M, C_, FF_, C_ / 128);
}

// round 13
// speedup vs baseline: 1.4661x; 1.0026x over previous
#include <cuda_runtime.h>
#include <cuda_fp16.h>
#include <cstdint>
#include <math.h>

// ---------------------------------------------------------------------------
// RWKV-v4 block: B=4, T=4096, C=2048, A=2048, FF=8192
// fp16 mma.sync (m16n8k16) GEMMs, fp32 accumulate, ldmatrix fragment loads,
// 256-thread CTAs (16 warps/SM) with 64x32 warp tiles for latency hiding.
// ---------------------------------------------------------------------------

#define B_  4
#define T_  4096
#define C_  2048
#define A_  2048
#define FF_ 8192

#define BTCll ((long long)B_ * T_ * C_)   // 33,554,432
#define BTFll ((long long)B_ * T_ * FF_)  // 134,217,728
#define ACll  ((long long)A_ * C_)        // 4,194,304
#define FCll  ((long long)FF_ * C_)       // 16,777,216

// float-unit layout:
// xk_h,xv_h,xr_h (BTC/2 each) | kk,vv,sr (BTC each) | sy_h (BTC/2)
// | kf_h (BTF/2) | hW (all fp16 weights, (5AC+2FC)/2)
__device__ float g_buf[262144000LL];

// ---------------------------------------------------------------------------
// helpers
// ---------------------------------------------------------------------------
__device__ __forceinline__ uint32_t s2u(const void* p) {
    return (uint32_t)__cvta_generic_to_shared(p);
}

__device__ __forceinline__ void cpa16(uint32_t dst, const void* src) {
    asm volatile("cp.async.cg.shared.global [%0], [%1], 16;" :: "r"(dst), "l"(src));
}

__device__ __forceinline__ void mma16(float c[4], const unsigned a[4], const unsigned b[2]) {
    asm volatile(
        "mma.sync.aligned.m16n8k16.row.col.f32.f16.f16.f32 "
        "{%0,%1,%2,%3}, {%4,%5,%6,%7}, {%8,%9}, {%0,%1,%2,%3};"
        : "+f"(c[0]), "+f"(c[1]), "+f"(c[2]), "+f"(c[3])
        : "r"(a[0]), "r"(a[1]), "r"(a[2]), "r"(a[3]), "r"(b[0]), "r"(b[1]));
}

#define LDSM4(rf, addr) \
    asm volatile("ldmatrix.sync.aligned.m8n8.x4.shared.b16 {%0,%1,%2,%3}, [%4];" \
        : "=r"((rf)[0]), "=r"((rf)[1]), "=r"((rf)[2]), "=r"((rf)[3]) : "r"(addr))

// ---------------------------------------------------------------------------
// Weight conversion fp32 -> fp16 (2 launches total)
// ---------------------------------------------------------------------------
__global__ __launch_bounds__(256) void conv_att_kernel(
    const float* __restrict__ w0, const float* __restrict__ w1,
    const float* __restrict__ w2, const float* __restrict__ w3,
    __half* __restrict__ d)  // 4 segments of AC floats each
{
    long long i4 = (long long)blockIdx.x * 256 + threadIdx.x;   // float4 index
    const long long segq = ACll / 4;
    int seg = (int)(i4 / segq);
    long long loc = (i4 - (long long)seg * segq) * 4;
    const float* s = (seg == 0) ? w0 : (seg == 1) ? w1 : (seg == 2) ? w2 : w3;
    float4 v = *(const float4*)(s + loc);
    __half2* o = (__half2*)(d + (long long)seg * ACll + loc);
    o[0] = __floats2half2_rn(v.x, v.y);
    o[1] = __floats2half2_rn(v.z, v.w);
}

__global__ __launch_bounds__(256) void conv_ffn_kernel(
    const float* __restrict__ wkf, const float* __restrict__ wrf,
    const float* __restrict__ wvf, __half* __restrict__ d)  // FC, AC, FC
{
    long long i4 = (long long)blockIdx.x * 256 + threadIdx.x;
    const long long q0 = FCll / 4, q1 = q0 + ACll / 4;
    const float* s;
    long long loc, dof;
    if (i4 < q0)      { s = wkf; loc = i4 * 4;        dof = loc; }
    else if (i4 < q1) { s = wrf; loc = (i4 - q0) * 4; dof = FCll + loc; }
    else              { s = wvf; loc = (i4 - q1) * 4; dof = FCll + ACll + loc; }
    float4 v = *(const float4*)(s + loc);
    __half2* o = (__half2*)(d + dof);
    o[0] = __floats2half2_rn(v.x, v.y);
    o[1] = __floats2half2_rn(v.z, v.w);
}

// ---------------------------------------------------------------------------
// Block reduce of 4 values (256 threads)
// ---------------------------------------------------------------------------
__device__ __forceinline__ void blockReduce4(float& a, float& b, float& c, float& d) {
    #pragma unroll
    for (int o = 16; o > 0; o >>= 1) {
        a += __shfl_down_sync(0xffffffffu, a, o);
        b += __shfl_down_sync(0xffffffffu, b, o);
        c += __shfl_down_sync(0xffffffffu, c, o);
        d += __shfl_down_sync(0xffffffffu, d, o);
    }
    __shared__ float sh[8][4];
    int w = threadIdx.x >> 5, l = threadIdx.x & 31;
    if (l == 0) { sh[w][0] = a; sh[w][1] = b; sh[w][2] = c; sh[w][3] = d; }
    __syncthreads();
    if (threadIdx.x == 0) {
        float ta = 0, tb = 0, tc = 0, td = 0;
        #pragma unroll
        for (int i = 0; i < 8; i++) { ta += sh[i][0]; tb += sh[i][1]; tc += sh[i][2]; td += sh[i][3]; }
        sh[0][0] = ta; sh[0][1] = tb; sh[0][2] = tc; sh[0][3] = td;
    }
    __syncthreads();
    a = sh[0][0]; b = sh[0][1]; c = sh[0][2]; d = sh[0][3];
}

// ---------------------------------------------------------------------------
// LayerNorm + shift mix -> fp16 outputs (GEMM A operands)
// ---------------------------------------------------------------------------
template <int NMIX>
__global__ __launch_bounds__(256) void ln_mix_kernel(
    const float* __restrict__ x, const float* __restrict__ shift_in,
    const float* __restrict__ gw, const float* __restrict__ bw,
    const float* __restrict__ m0, const float* __restrict__ m1, const float* __restrict__ m2,
    __half* __restrict__ o0, __half* __restrict__ o1, __half* __restrict__ o2,
    float* __restrict__ shift_out)
{
    const int bt = blockIdx.x;
    const int b = bt / T_, t = bt % T_;
    const int tid = threadIdx.x;
    const float* xr = x + (long long)bt * C_;

    float cur[8], prv[8];
    float s1 = 0.f, s2 = 0.f, p1 = 0.f, p2 = 0.f;
    #pragma unroll
    for (int i = 0; i < 8; i++) {
        int c = tid + i * 256;
        float v = xr[c];
        cur[i] = v; s1 += v; s2 += v * v;
        if (t > 0) {
            float w = xr[c - C_];
            prv[i] = w; p1 += w; p2 += w * w;
        } else prv[i] = 0.f;
    }
    blockReduce4(s1, s2, p1, p2);
    const float inv = 1.f / (float)C_;
    float mu = s1 * inv;
    float rs = rsqrtf(s2 * inv - mu * mu + 1e-5f);
    float mup = 0.f, rsp = 0.f;
    if (t > 0) {
        mup = p1 * inv;
        rsp = rsqrtf(p2 * inv - mup * mup + 1e-5f);
    }
    long long o = (long long)bt * C_;
    #pragma unroll
    for (int i = 0; i < 8; i++) {
        int c = tid + i * 256;
        float gg = gw[c], bb = bw[c];
        float xn = (cur[i] - mu) * rs * gg + bb;
        float xx = (t > 0) ? ((prv[i] - mup) * rsp * gg + bb)
                           : shift_in[(long long)b * C_ + c];
        float a0 = m0[c]; o0[o + c] = __float2half_rn(xn * a0 + xx * (1.f - a0));
        float a1 = m1[c]; o1[o + c] = __float2half_rn(xn * a1 + xx * (1.f - a1));
        if (NMIX == 3) { float a2 = m2[c]; o2[o + c] = __float2half_rn(xn * a2 + xx * (1.f - a2)); }
        if (t == T_ - 1) shift_out[(long long)b * C_ + c] = xn;
    }
}

// ---------------------------------------------------------------------------
// WKV scan: one thread per (b,channel); sy emitted as fp16 for the Wo GEMM
// ---------------------------------------------------------------------------
__global__ __launch_bounds__(64) void wkv_scan_kernel(
    const float* __restrict__ k, const float* __restrict__ v,
    const float* __restrict__ sr,
    const float* __restrict__ td, const float* __restrict__ tf,
    const float* __restrict__ state,
    __half* __restrict__ sy, float* __restrict__ out_wkv)
{
    int i = blockIdx.x * blockDim.x + threadIdx.x;  // b*A + a
    int b = i / A_, a = i % A_;
    float w = -expf(td[a]);
    float u = tf[a];
    long long so = ((long long)b * C_ + a) * 3;
    float aa = state[so + 0];
    float bb = state[so + 1];
    float pp = state[so + 2];
    long long o = (long long)b * T_ * A_ + a;
    float kt = k[o], vt = v[o], rt = sr[o];
    for (int t = 0; t < T_; t++) {
        long long on = o + A_;
        float kn = 0.f, vn = 0.f, rn = 0.f;
        if (t + 1 < T_) { kn = k[on]; vn = v[on]; rn = sr[on]; }
        float ww = u + kt;
        float p  = fmaxf(pp, ww);
        float e1 = __expf(pp - p);
        float e2 = __expf(ww - p);
        float y  = __fdividef(e1 * aa + e2 * vt, e1 * bb + e2);
        sy[o] = __float2half_rn(rt * y);
        float ww2 = pp + w;
        float p2  = fmaxf(ww2, kt);
        e1 = __expf(ww2 - p2);
        e2 = __expf(kt - p2);
        aa = e1 * aa + e2 * vt;
        bb = e1 * bb + e2;
        pp = p2;
        o = on; kt = kn; vt = vn; rt = rn;
    }
    out_wkv[so + 0] = aa;
    out_wkv[so + 1] = bb;
    out_wkv[so + 2] = pp;
}

// ---------------------------------------------------------------------------
// FP16 NT GEMM via mma.sync m16n8k16: out[m,n] = sum_k A[m,k]*B[n,k]
// CTA 128x128x64, 256 threads (8 warps, warp tile 64x32, grid 2x4),
// cp.async 3-stage, single-buffered ldmatrix fragment loads.
// MODE: 0=store f32, 1=sigmoid f32, 2=relu^2 -> fp16, 3=base+acc, 4=base+mul*acc
// ---------------------------------------------------------------------------
#define GBK   64
#define HSTR  72                               // halfs per smem row (64+8 pad)
#define STG_H (2 * 128 * HSTR)                 // A+B rows per stage, in halfs
#define NSTG  3
#define GEMM_SMEM (NSTG * STG_H * 2)           // 110592 B -> 2 CTAs/SM

template <int MODE>
__global__ __launch_bounds__(256, 2) void gemm_h(
    const __half* __restrict__ Ag, const __half* __restrict__ Bg,
    void* __restrict__ Ogv,
    const float* __restrict__ base, const float* __restrict__ mul,
    int M, int N, int K, int tiles_n)
{
    extern __shared__ __half sm[];

    const int tid  = threadIdx.x;
    const int lane = tid & 31;
    const int warp = tid >> 5;            // 0..7
    const int wm   = (warp & 1) * 64;
    const int wn   = (warp >> 1) * 32;
    const int gid  = lane >> 2;           // 0..7
    const int tig  = lane & 3;            // 0..3

    // rasterization: groups of 16 M-tiles; consecutive blocks share B tile
    const int per = 16 * tiles_n;
    const int grp = blockIdx.x / per, rem = blockIdx.x % per;
    const int mt = grp * 16 + (rem % 16);
    const int nt = rem / 16;
    const long long bm0 = (long long)mt * 128, bn0 = (long long)nt * 128;

    const int ldr = tid >> 3;             // 0..31 base row
    const int ldh = (tid & 7) * 8;        // half col {0,8,...,56}

    const uint32_t sbase = s2u(sm);

    // ldmatrix per-thread offsets (bytes). q = address-group, r = row in group.
    const int q = lane >> 3, r = lane & 7;
    const uint32_t aoff = (uint32_t)(((wm + (q & 1) * 8 + r) * HSTR + (q >> 1) * 8) * 2);
    const uint32_t boff = (uint32_t)((128 * HSTR + (wn + (q >> 1) * 8 + r) * HSTR + (q & 1) * 8) * 2);

    auto load_stage = [&](int j) {
        __half* As = sm + (j % NSTG) * STG_H;
        __half* Bs = As + 128 * HSTR;
        const long long k0 = (long long)j * GBK;
        const __half* Ap = Ag + (bm0 + ldr) * K + k0 + ldh;
        const __half* Bp = Bg + (bn0 + ldr) * K + k0 + ldh;
        uint32_t da = s2u(As + ldr * HSTR + ldh);
        uint32_t db = s2u(Bs + ldr * HSTR + ldh);
        #pragma unroll
        for (int i = 0; i < 4; i++) {
            cpa16(da + i * 32 * HSTR * 2, Ap + (long long)i * 32 * K);
            cpa16(db + i * 32 * HSTR * 2, Bp + (long long)i * 32 * K);
        }
    };

    float acc[4][4][4];
    #pragma unroll
    for (int mi = 0; mi < 4; mi++)
        #pragma unroll
        for (int ni = 0; ni < 4; ni++)
            #pragma unroll
            for (int qq = 0; qq < 4; qq++) acc[mi][ni][qq] = 0.f;

    const int nk = K >> 6;
    load_stage(0);
    asm volatile("cp.async.commit_group;" ::: "memory");
    load_stage(1);
    asm volatile("cp.async.commit_group;" ::: "memory");

    unsigned af[4][4];        // [mi][frag]
    unsigned bf[2][4];        // [ni-pair][frag] = {b[2p][0],b[2p][1],b[2p+1][0],b[2p+1][1]}

    for (int j = 0; j < nk; j++) {
        asm volatile("cp.async.wait_group 1;" ::: "memory");
        __syncthreads();
        if (j + 2 < nk) load_stage(j + 2);
        asm volatile("cp.async.commit_group;" ::: "memory");

        const uint32_t sa = sbase + (uint32_t)((j % NSTG) * STG_H * 2) + aoff;
        const uint32_t sb = sbase + (uint32_t)((j % NSTG) * STG_H * 2) + boff;

        #pragma unroll
        for (int ks = 0; ks < 4; ks++) {
            const uint32_t ko = (uint32_t)(ks * 32);   // 16 halfs in bytes
            #pragma unroll
            for (int mi = 0; mi < 4; mi++) LDSM4(af[mi], sa + mi * (16 * HSTR * 2) + ko);
            #pragma unroll
            for (int pi = 0; pi < 2; pi++) LDSM4(bf[pi], sb + pi * (16 * HSTR * 2) + ko);
            #pragma unroll
            for (int mi = 0; mi < 4; mi++)
                #pragma unroll
                for (int ni = 0; ni < 4; ni++)
                    mma16(acc[mi][ni], af[mi], &bf[ni >> 1][(ni & 1) * 2]);
        }
    }

    // epilogue
    #pragma unroll
    for (int mi = 0; mi < 4; mi++) {
        #pragma unroll
        for (int ni = 0; ni < 4; ni++) {
            long long row = bm0 + wm + mi * 16 + gid;
            long long col = bn0 + wn + ni * 8 + 2 * tig;
            long long i0 = row * N + col;
            long long i1 = (row + 8) * N + col;
            float v00 = acc[mi][ni][0], v01 = acc[mi][ni][1];
            float v10 = acc[mi][ni][2], v11 = acc[mi][ni][3];
            if (MODE == 1) {
                v00 = 1.f / (1.f + __expf(-v00)); v01 = 1.f / (1.f + __expf(-v01));
                v10 = 1.f / (1.f + __expf(-v10)); v11 = 1.f / (1.f + __expf(-v11));
            } else if (MODE == 3) {
                v00 += base[i0]; v01 += base[i0 + 1];
                v10 += base[i1]; v11 += base[i1 + 1];
            } else if (MODE == 4) {
                v00 = fmaf(mul[i0], v00, base[i0]);
                v01 = fmaf(mul[i0 + 1], v01, base[i0 + 1]);
                v10 = fmaf(mul[i1], v10, base[i1]);
                v11 = fmaf(mul[i1 + 1], v11, base[i1 + 1]);
            }
            if (MODE == 2) {
                __half* Og = (__half*)Ogv;
                float t00 = fmaxf(v00, 0.f), t01 = fmaxf(v01, 0.f);
                float t10 = fmaxf(v10, 0.f), t11 = fmaxf(v11, 0.f);
                *(__half2*)(Og + i0) = __floats2half2_rn(t00 * t00, t01 * t01);
                *(__half2*)(Og + i1) = __floats2half2_rn(t10 * t10, t11 * t11);
            } else {
                float* Og = (float*)Ogv;
                *(float2*)(Og + i0) = make_float2(v00, v01);
                *(float2*)(Og + i1) = make_float2(v10, v11);
            }
        }
    }
}

// ---------------------------------------------------------------------------
// Launcher
// ---------------------------------------------------------------------------
extern "C" void kernel_launch(void* const* d_in, const int* in_sizes, int n_in,
                              void* d_out, int out_size)
{
    const float* x    = (const float*)d_in[0];
    const float* tm   = (const float*)d_in[1];
    const float* st   = (const float*)d_in[2];
    const float* cm   = (const float*)d_in[3];
    const float* g1   = (const float*)d_in[4];
    const float* b1   = (const float*)d_in[5];
    const float* g2   = (const float*)d_in[6];
    const float* b2   = (const float*)d_in[7];
    const float* td   = (const float*)d_in[8];
    const float* tfst = (const float*)d_in[9];
    const float* amk  = (const float*)d_in[10];
    const float* amv  = (const float*)d_in[11];
    const float* amr  = (const float*)d_in[12];
    const float* Wk   = (const float*)d_in[13];
    const float* Wv   = (const float*)d_in[14];
    const float* Wr   = (const float*)d_in[15];
    const float* Wo   = (const float*)d_in[16];
    const float* fmk  = (const float*)d_in[17];
    const float* fmr  = (const float*)d_in[18];
    const float* Wkf  = (const float*)d_in[19];
    const float* Wrf  = (const float*)d_in[20];
    const float* Wvf  = (const float*)d_in[21];

    float* out     = (float*)d_out;
    float* out_x   = out;
    float* out_wkv = out + BTCll;
    float* out_tm  = out_wkv + (long long)B_ * C_ * 3;
    float* out_cm  = out_tm + (long long)B_ * C_;

    float* buf = nullptr;
    cudaGetSymbolAddress((void**)&buf, g_buf);
    __half* xk_h = (__half*)(buf);
    __half* xv_h = xk_h + BTCll;
    __half* xr_h = xv_h + BTCll;
    float*  kk   = buf + 3 * (BTCll / 2);
    float*  vv   = kk + BTCll;
    float*  sr   = vv + BTCll;
    __half* sy_h = (__half*)(sr + BTCll);
    __half* kf_h = sy_h + BTCll;
    __half* hW   = kf_h + BTFll;
    __half* hWk  = hW;
    __half* hWv  = hWk + ACll;
    __half* hWr  = hWv + ACll;
    __half* hWo  = hWr + ACll;
    __half* hWkf = hWo + ACll;
    __half* hWrf = hWkf + FCll;
    __half* hWvf = hWrf + ACll;

    cudaFuncSetAttribute((const void*)gemm_h<0>, cudaFuncAttributeMaxDynamicSharedMemorySize, GEMM_SMEM);
    cudaFuncSetAttribute((const void*)gemm_h<1>, cudaFuncAttributeMaxDynamicSharedMemorySize, GEMM_SMEM);
    cudaFuncSetAttribute((const void*)gemm_h<2>, cudaFuncAttributeMaxDynamicSharedMemorySize, GEMM_SMEM);
    cudaFuncSetAttribute((const void*)gemm_h<3>, cudaFuncAttributeMaxDynamicSharedMemorySize, GEMM_SMEM);
    cudaFuncSetAttribute((const void*)gemm_h<4>, cudaFuncAttributeMaxDynamicSharedMemorySize, GEMM_SMEM);

    const int M = B_ * T_;
    const int tm_ = M / 128;

    // weight fp32 -> fp16 (2 launches)
    conv_att_kernel<<<(int)(4 * ACll / 4 / 256), 256>>>(Wk, Wv, Wr, Wo, hW);
    conv_ffn_kernel<<<(int)((2 * FCll + ACll) / 4 / 256), 256>>>(Wkf, Wrf, Wvf, hWkf);

    // --- attention path ---
    ln_mix_kernel<3><<<M, 256>>>(x, tm, g1, b1, amk, amv, amr, xk_h, xv_h, xr_h, out_tm);

    gemm_h<0><<<tm_ * (A_ / 128), 256, GEMM_SMEM>>>(xk_h, hWk, kk, nullptr, nullptr, M, A_, C_, A_ / 128);
    gemm_h<0><<<tm_ * (A_ / 128), 256, GEMM_SMEM>>>(xv_h, hWv, vv, nullptr, nullptr, M, A_, C_, A_ / 128);
    gemm_h<1><<<tm_ * (A_ / 128), 256, GEMM_SMEM>>>(xr_h, hWr, sr, nullptr, nullptr, M, A_, C_, A_ / 128);

    wkv_scan_kernel<<<(B_ * A_) / 64, 64>>>(kk, vv, sr, td, tfst, st, sy_h, out_wkv);

    gemm_h<3><<<tm_ * (C_ / 128), 256, GEMM_SMEM>>>(sy_h, hWo, out_x, x, nullptr, M, C_, A_, C_ / 128);

    // --- ffn path ---
    ln_mix_kernel<2><<<M, 256>>>(out_x, cm, g2, b2, fmk, fmr, nullptr, xk_h, xr_h, nullptr, out_cm);

    gemm_h<2><<<tm_ * (FF_ / 128), 256, GEMM_SMEM>>>(xk_h, hWkf, kf_h, nullptr, nullptr, M, FF_, C_, FF_ / 128);
    gemm_h<1><<<tm_ * (C_ / 128), 256, GEMM_SMEM>>>(xr_h, hWrf, vv, nullptr, nullptr, M, C_, C_, C_ / 128);
    gemm_h<4><<<tm_ * (C_ / 128), 256, GEMM_SMEM>>>(kf_h, hWvf, out_x, out_x, vv, M, C_, FF_, C_ / 128);
}